// round 6
// baseline (speedup 1.0000x reference)
#include <cuda_runtime.h>
#include <cuda_bf16.h>
#include <cstdint>

#define Tn 4096   // B*S tokens
#define Dn 1024
#define En 8
#define Fn 4096
#define Bb 8
#define Sn 512

// ---------------- scratch (device globals; no allocations) ----------------
__device__ float g_lin[Tn * Dn];
__device__ __nv_bfloat16 g_linb[Tn * Dn];
__device__ float g_accb[Tn * Dn];
__device__ __nv_bfloat16 g_hb[2 * Tn * Fn];
__device__ __nv_bfloat16 g_w1b[(size_t)En * Dn * Fn];
__device__ __nv_bfloat16 g_w2b[(size_t)En * Fn * Dn];
__device__ int   g_tok[2 * Tn];
__device__ float g_tw[2 * Tn];
__device__ int   g_cnt[En], g_off[En], g_fill[En];
__device__ int   g_gi[Tn * 2];
__device__ float g_gw[Tn * 2];
__device__ float g_sent[Bb * Dn];

// ---------------- mma helpers ----------------
__device__ __forceinline__ uint32_t s2u(const void* p) {
    uint32_t a;
    asm("{ .reg .u64 t; cvta.to.shared.u64 t, %1; cvt.u32.u64 %0, t; }" : "=r"(a) : "l"(p));
    return a;
}
__device__ __forceinline__ void mma16(float* c, const uint32_t* a,
                                      uint32_t b0, uint32_t b1) {
    asm volatile(
        "mma.sync.aligned.m16n8k16.row.col.f32.bf16.bf16.f32 "
        "{%0,%1,%2,%3},{%4,%5,%6,%7},{%8,%9},{%0,%1,%2,%3};"
        : "+f"(c[0]), "+f"(c[1]), "+f"(c[2]), "+f"(c[3])
        : "r"(a[0]), "r"(a[1]), "r"(a[2]), "r"(a[3]), "r"(b0), "r"(b1));
}
__device__ __forceinline__ void ldmx4(uint32_t* r, uint32_t a) {
    asm volatile("ldmatrix.sync.aligned.m8n8.x4.shared.b16 {%0,%1,%2,%3},[%4];"
                 : "=r"(r[0]), "=r"(r[1]), "=r"(r[2]), "=r"(r[3]) : "r"(a));
}
__device__ __forceinline__ void ldmx4t(uint32_t* r, uint32_t a) {
    asm volatile("ldmatrix.sync.aligned.m8n8.x4.trans.shared.b16 {%0,%1,%2,%3},[%4];"
                 : "=r"(r[0]), "=r"(r[1]), "=r"(r[2]), "=r"(r[3]) : "r"(a));
}

// ---------------- fp32 -> bf16 weight conversion ----------------
__global__ void k_cvt(const float* __restrict__ s, __nv_bfloat16* __restrict__ d, int n) {
    int i = (blockIdx.x * blockDim.x + threadIdx.x) * 4;
    int st = gridDim.x * blockDim.x * 4;
    for (; i < n; i += st) {
        float4 v = *(const float4*)(s + i);
        *(__nv_bfloat162*)(d + i)     = __floats2bfloat162_rn(v.x, v.y);
        *(__nv_bfloat162*)(d + i + 2) = __floats2bfloat162_rn(v.z, v.w);
    }
}

// ---------------- init: acc = x, zero expert counters ----------------
__global__ void k_init(const float* __restrict__ x) {
    if (blockIdx.x == 0 && threadIdx.x < En) g_cnt[threadIdx.x] = 0;
    int st = gridDim.x * blockDim.x;
    for (int i = blockIdx.x * blockDim.x + threadIdx.x; i < Tn * Dn; i += st)
        g_accb[i] = x[i];
}

// ---------------- lin = x @ W^T + b (fp32 exact; feeds gate) ----------------
__global__ void __launch_bounds__(256) k_gemm_lin(
    const float* __restrict__ x, const float* __restrict__ W,
    const float* __restrict__ bias)
{
    __shared__ float As[16][132];
    __shared__ float Bs[16][132];
    int row0 = blockIdx.y * 128, col0 = blockIdx.x * 128;
    int tid = threadIdx.x;
    int rA = tid >> 2, k4 = (tid & 3) * 4;
    int ty = tid >> 4, tx = tid & 15;
    float cc[8][8] = {};
    for (int k0 = 0; k0 < Dn; k0 += 16) {
        float4 va = *(const float4*)&x[(size_t)(row0 + rA) * Dn + k0 + k4];
        As[k4 + 0][rA] = va.x; As[k4 + 1][rA] = va.y;
        As[k4 + 2][rA] = va.z; As[k4 + 3][rA] = va.w;
        float4 vb = *(const float4*)&x[(size_t)(row0 + rA + 64) * Dn + k0 + k4];
        As[k4 + 0][rA + 64] = vb.x; As[k4 + 1][rA + 64] = vb.y;
        As[k4 + 2][rA + 64] = vb.z; As[k4 + 3][rA + 64] = vb.w;
        float4 w0 = *(const float4*)&W[(size_t)(col0 + rA) * Dn + k0 + k4];
        Bs[k4 + 0][rA] = w0.x; Bs[k4 + 1][rA] = w0.y;
        Bs[k4 + 2][rA] = w0.z; Bs[k4 + 3][rA] = w0.w;
        float4 w1v = *(const float4*)&W[(size_t)(col0 + rA + 64) * Dn + k0 + k4];
        Bs[k4 + 0][rA + 64] = w1v.x; Bs[k4 + 1][rA + 64] = w1v.y;
        Bs[k4 + 2][rA + 64] = w1v.z; Bs[k4 + 3][rA + 64] = w1v.w;
        __syncthreads();
#pragma unroll
        for (int k = 0; k < 16; k++) {
            float4 a0 = *(float4*)&As[k][ty * 8], a1 = *(float4*)&As[k][ty * 8 + 4];
            float4 b0 = *(float4*)&Bs[k][tx * 8], b1 = *(float4*)&Bs[k][tx * 8 + 4];
            float ra[8] = {a0.x, a0.y, a0.z, a0.w, a1.x, a1.y, a1.z, a1.w};
            float rb[8] = {b0.x, b0.y, b0.z, b0.w, b1.x, b1.y, b1.z, b1.w};
#pragma unroll
            for (int i = 0; i < 8; i++)
#pragma unroll
                for (int j = 0; j < 8; j++) cc[i][j] += ra[i] * rb[j];
        }
        __syncthreads();
    }
#pragma unroll
    for (int i = 0; i < 8; i++) {
        int row = row0 + ty * 8 + i;
        float* c = &g_lin[(size_t)row * Dn + col0 + tx * 8];
        __nv_bfloat16* cb = &g_linb[(size_t)row * Dn + col0 + tx * 8];
#pragma unroll
        for (int j = 0; j < 8; j += 2) {
            float v0 = cc[i][j] + bias[col0 + tx * 8 + j];
            float v1 = cc[i][j + 1] + bias[col0 + tx * 8 + j + 1];
            c[j] = v0; c[j + 1] = v1;
            *(__nv_bfloat162*)(cb + j) = __floats2bfloat162_rn(v0, v1);
        }
    }
}

// ---------------- gate: exact fp32 top-2 ----------------
__global__ void k_gate(const float* __restrict__ Wg) {
    int warp = (blockIdx.x * blockDim.x + threadIdx.x) >> 5;
    int lane = threadIdx.x & 31;
    if (warp >= Tn) return;
    const float* lr = &g_lin[(size_t)warp * Dn];
    float p[En] = {};
    for (int i = lane; i < Dn; i += 32) {
        float v = lr[i];
        const float* w = &Wg[i * En];
#pragma unroll
        for (int e = 0; e < En; e++) p[e] += v * w[e];
    }
#pragma unroll
    for (int o = 16; o; o >>= 1)
#pragma unroll
        for (int e = 0; e < En; e++) p[e] += __shfl_xor_sync(0xffffffffu, p[e], o);
    if (lane == 0) {
        int i1 = 0;
        for (int e = 1; e < En; e++) if (p[e] > p[i1]) i1 = e;
        int i2 = -1;
        for (int e = 0; e < En; e++)
            if (e != i1 && (i2 < 0 || p[e] > p[i2])) i2 = e;
        float w1 = 1.f / (1.f + expf(p[i2] - p[i1]));
        g_gi[warp * 2] = i1; g_gi[warp * 2 + 1] = i2;
        g_gw[warp * 2] = w1; g_gw[warp * 2 + 1] = 1.f - w1;
        atomicAdd(&g_cnt[i1], 1);
        atomicAdd(&g_cnt[i2], 1);
    }
}

__global__ void k_off() {
    int a = 0;
    for (int e = 0; e < En; e++) { g_off[e] = a; a += g_cnt[e]; g_fill[e] = 0; }
}

__global__ void k_scatter() {
    int t = blockIdx.x * blockDim.x + threadIdx.x;
    if (t >= Tn) return;
#pragma unroll
    for (int k = 0; k < 2; k++) {
        int e = g_gi[t * 2 + k];
        int slot = g_off[e] + atomicAdd(&g_fill[e], 1);
        g_tok[slot] = t;
        g_tw[slot]  = g_gw[t * 2 + k];
    }
}

// ==== bf16 mma.sync grouped GEMM: 128x128 tile, Kc=32, ldmatrix feeds ======
// MODE 1: g_hb = relu(linb[g_tok] @ w1b[e] + b1)   (KD=Dn, NT=Fn)
// MODE 2: g_accb += gw * (g_hb @ w2b[e] + b2)      (KD=Fn, NT=Dn)
template<int KD, int NT, int MODE>
__global__ void __launch_bounds__(256) mma_ffn(const __nv_bfloat16* __restrict__ Bw,
                                               const float* __restrict__ bias)
{
    __shared__ __align__(16) __nv_bfloat16 As[128 * 40];  // 80B row stride (64B data+pad)
    __shared__ __align__(16) __nv_bfloat16 Bs[32 * 136];  // 272B row stride (256B data+pad)
    int e = blockIdx.z, cnt = g_cnt[e], row0 = blockIdx.x * 128;
    if (row0 >= cnt) return;
    int off = g_off[e], col0 = blockIdx.y * 128;
    int tid = threadIdx.x, warp = tid >> 5, lane = tid & 31;
    int warpM = warp >> 1, warpN = warp & 1;
    int grp = lane >> 2, tig = lane & 3;
    int mBase = warpM * 32, nBase = warpN * 64;

    uint32_t Au = s2u(As), Bu = s2u(Bs);
    uint32_t aoff = Au + (uint32_t)(mBase + (lane & 15)) * 80 + (lane >> 4) * 16;
    uint32_t boff = Bu + (uint32_t)(lane & 15) * 272 + (lane >> 4) * 16 + nBase * 2;

    // staging: A row rs (2 threads/row, 32B each), B k-row bkr (8 threads/row)
    int rs = tid >> 1, aq = (tid & 1) * 32;
    const __nv_bfloat16* asrc;
    if (MODE == 1) {
        int r = row0 + rs;
        int tok = (r < cnt) ? g_tok[off + r] : 0;
        asrc = g_linb + (size_t)tok * KD;
    } else {
        int s = off + row0 + rs; if (s >= 2 * Tn) s = 0;
        asrc = g_hb + (size_t)s * KD;
    }
    int bkr = tid >> 3, bc = tid & 7;
    const __nv_bfloat16* bsrc = Bw + (size_t)e * KD * NT + (size_t)bkr * NT + col0;

    float cc[2][8][4] = {};
    uint4 ra0, ra1, rb0, rb1;
    {
        const uint4* ap = (const uint4*)asrc;
        ra0 = ap[aq >> 4]; ra1 = ap[(aq >> 4) + 1];
        const uint4* bp = (const uint4*)bsrc;
        rb0 = bp[bc]; rb1 = bp[bc + 8];
    }
    const int NK = KD / 32;
    for (int it = 0; it < NK; ++it) {
        *(uint4*)((char*)As + rs * 80 + aq)        = ra0;
        *(uint4*)((char*)As + rs * 80 + aq + 16)   = ra1;
        *(uint4*)((char*)Bs + bkr * 272 + bc * 16)       = rb0;
        *(uint4*)((char*)Bs + bkr * 272 + (bc + 8) * 16) = rb1;
        __syncthreads();
        if (it + 1 < NK) {
            int k0 = (it + 1) * 32;
            const uint4* ap = (const uint4*)(asrc + k0);
            ra0 = ap[aq >> 4]; ra1 = ap[(aq >> 4) + 1];
            const uint4* bp = (const uint4*)(bsrc + (size_t)k0 * NT);
            rb0 = bp[bc]; rb1 = bp[bc + 8];
        }
#pragma unroll
        for (int ks = 0; ks < 32; ks += 16) {
            uint32_t af[2][4], bf[4][4];
#pragma unroll
            for (int mt = 0; mt < 2; mt++)
                ldmx4(af[mt], aoff + mt * (16 * 80) + ks * 2);
#pragma unroll
            for (int p = 0; p < 4; p++)
                ldmx4t(bf[p], boff + ks * 272 + p * 32);
#pragma unroll
            for (int mt = 0; mt < 2; mt++)
#pragma unroll
                for (int p = 0; p < 4; p++) {
                    mma16(cc[mt][2 * p],     af[mt], bf[p][0], bf[p][1]);
                    mma16(cc[mt][2 * p + 1], af[mt], bf[p][2], bf[p][3]);
                }
        }
        __syncthreads();
    }

    // epilogue: c0,c1 -> row grp; c2,c3 -> row grp+8; cols 2*tig, 2*tig+1
#pragma unroll
    for (int mt = 0; mt < 2; mt++)
#pragma unroll
    for (int half = 0; half < 2; half++) {
        int r = row0 + mBase + mt * 16 + grp + half * 8;
        if (r >= cnt) continue;
        int slot = off + r;
        if (MODE == 1) {
            __nv_bfloat16* o = g_hb + (size_t)slot * Fn + col0;
#pragma unroll
            for (int nt = 0; nt < 8; nt++) {
                int c = nBase + nt * 8 + 2 * tig;
                float vx = fmaxf(cc[mt][nt][half * 2 + 0] + bias[e * Fn + col0 + c], 0.f);
                float vy = fmaxf(cc[mt][nt][half * 2 + 1] + bias[e * Fn + col0 + c + 1], 0.f);
                *(__nv_bfloat162*)(o + c) = __floats2bfloat162_rn(vx, vy);
            }
        } else {
            int tok = g_tok[slot];
            float gw = g_tw[slot];
            float* o = g_accb + (size_t)tok * Dn + col0;
#pragma unroll
            for (int nt = 0; nt < 8; nt++) {
                int c = nBase + nt * 8 + 2 * tig;
                atomicAdd(&o[c],     gw * (cc[mt][nt][half * 2 + 0] + bias[e * Dn + col0 + c]));
                atomicAdd(&o[c + 1], gw * (cc[mt][nt][half * 2 + 1] + bias[e * Dn + col0 + c + 1]));
            }
        }
    }
}

// ---------------- mean pool + loss ----------------
__global__ void k_sent(float* out) {
    int i = blockIdx.x * blockDim.x + threadIdx.x;
    if (i == 0) out[0] = 0.f;
    if (i >= Bb * Dn) return;
    int b = i >> 10, d = i & 1023;
    const float* p = &g_accb[(size_t)(b * Sn) * Dn + d];
    float s = 0.f;
    for (int si = 0; si < Sn; si++) s += p[si * Dn];
    g_sent[i] = s * (1.f / Sn);
}

__global__ void k_loss(const int* __restrict__ y, float* out) {
    int b = blockIdx.x, tid = threadIdx.x;
    __shared__ float red[256];
    const float* s = &g_sent[b * Dn];
    float m = -1e30f;
    for (int i = tid; i < Dn; i += 256) m = fmaxf(m, s[i]);
    red[tid] = m; __syncthreads();
    for (int o = 128; o; o >>= 1) {
        if (tid < o) red[tid] = fmaxf(red[tid], red[tid + o]);
        __syncthreads();
    }
    float mx = red[0]; __syncthreads();
    float sum = 0.f;
    for (int i = tid; i < Dn; i += 256) sum += expf(s[i] - mx);
    red[tid] = sum; __syncthreads();
    for (int o = 128; o; o >>= 1) {
        if (tid < o) red[tid] += red[tid + o];
        __syncthreads();
    }
    if (tid == 0)
        atomicAdd(out, -(s[y[b]] - (mx + logf(red[0]))) * (1.f / Bb));
}

// ---------------- launch ----------------
extern "C" void kernel_launch(void* const* d_in, const int* in_sizes, int n_in,
                              void* d_out, int out_size) {
    const float* x  = (const float*)d_in[0];
    const int*   y  = (const int*)d_in[1];
    const float* W  = (const float*)d_in[2];
    const float* bb = (const float*)d_in[3];
    const float* Wg = (const float*)d_in[4];
    const float* w1 = (const float*)d_in[5];
    const float* b1 = (const float*)d_in[6];
    const float* w2 = (const float*)d_in[7];
    const float* b2 = (const float*)d_in[8];
    float* out = (float*)d_out;

    const int NW = En * Dn * Fn;
    k_cvt<<<4096, 256>>>(w1, g_w1b, NW);
    k_cvt<<<4096, 256>>>(w2, g_w2b, NW);
    k_init<<<256, 256>>>(x);
    k_gemm_lin<<<dim3(Dn / 128, Tn / 128), 256>>>(x, W, bb);
    k_gate<<<(Tn * 32) / 256, 256>>>(Wg);
    k_off<<<1, 1>>>();
    k_scatter<<<Tn / 256, 256>>>();
    mma_ffn<Dn, Fn, 1><<<dim3(Tn / 128, Fn / 128, En), 256>>>(g_w1b, b1);
    mma_ffn<Fn, Dn, 2><<<dim3(Tn / 128, Dn / 128, En), 256>>>(g_w2b, b2);
    k_sent<<<(Bb * Dn + 255) / 256, 256>>>(out);
    k_loss<<<Bb, 256>>>(y, out);
}

// round 7
// speedup vs baseline: 5.0833x; 5.0833x over previous
#include <cuda_runtime.h>
#include <cstdint>

#define Tn 4096   // B*S tokens
#define Dn 1024
#define En 8
#define Fn 4096
#define Bb 8
#define Sn 512

// ---------------- scratch (device globals; no allocations) ----------------
__device__ float g_lin[Tn * Dn];
__device__ float g_accb[Tn * Dn];          // moe accumulation only (zeroed)
__device__ float g_h[2 * Tn * Fn];
__device__ float g_wc[Dn * En];            // folded gate weight x@Wc = gate logits
__device__ float g_bc[En];
__device__ int   g_tok[2 * Tn];
__device__ float g_tw[2 * Tn];
__device__ int   g_cnt[En], g_off[En], g_fill[En];
__device__ int   g_gi[Tn * 2];
__device__ float g_gw[Tn * 2];
__device__ float g_sent[Bb * Dn];

// ---------------- tf32 helpers ----------------
__device__ __forceinline__ float tf32r(float v) {
    uint32_t r;
    asm("cvt.rna.tf32.f32 %0, %1;" : "=r"(r) : "f"(v));
    return __uint_as_float(r);
}
__device__ __forceinline__ void mma8(float* c, const uint32_t* a,
                                     uint32_t b0, uint32_t b1) {
    asm volatile(
        "mma.sync.aligned.m16n8k8.row.col.f32.tf32.tf32.f32 "
        "{%0,%1,%2,%3},{%4,%5,%6,%7},{%8,%9},{%0,%1,%2,%3};"
        : "+f"(c[0]), "+f"(c[1]), "+f"(c[2]), "+f"(c[3])
        : "r"(a[0]), "r"(a[1]), "r"(a[2]), "r"(a[3]), "r"(b0), "r"(b1));
}

// ---------------- Wc = W^T @ Wg (exact fp32), bc = b @ Wg ----------------
__global__ void __launch_bounds__(256) k_wc(const float* __restrict__ W,
                                            const float* __restrict__ Wg,
                                            const float* __restrict__ b) {
    __shared__ float swg[Dn * En];          // 32 KB
    for (int i = threadIdx.x; i < Dn * En; i += 256) swg[i] = Wg[i];
    __syncthreads();
    int d = blockIdx.x * 256 + threadIdx.x;
    float acc[En] = {};
    for (int ep = 0; ep < Dn; ep++) {
        float wv = W[(size_t)ep * Dn + d];
        const float* wg = &swg[ep * En];
#pragma unroll
        for (int e = 0; e < En; e++) acc[e] += wv * wg[e];
    }
#pragma unroll
    for (int e = 0; e < En; e++) g_wc[d * En + e] = acc[e];
    if (blockIdx.x == 0 && threadIdx.x < En) {
        float s = 0.f;
        for (int ep = 0; ep < Dn; ep++) s += b[ep] * swg[ep * En + threadIdx.x];
        g_bc[threadIdx.x] = s;
    }
}

// ---------------- init: zero moe accumulator + counters ----------------
__global__ void k_init() {
    if (blockIdx.x == 0 && threadIdx.x < En) g_cnt[threadIdx.x] = 0;
    int st = gridDim.x * blockDim.x;
    for (int i = blockIdx.x * blockDim.x + threadIdx.x; i < Tn * Dn; i += st)
        g_accb[i] = 0.f;
}

// ---------------- gate from x via folded Wc (exact fp32 top-2) -------------
__global__ void k_gate2(const float* __restrict__ x) {
    int warp = (blockIdx.x * blockDim.x + threadIdx.x) >> 5;
    int lane = threadIdx.x & 31;
    if (warp >= Tn) return;
    const float* xr = &x[(size_t)warp * Dn];
    float p[En] = {};
    for (int i = lane; i < Dn; i += 32) {
        float v = xr[i];
        const float* w = &g_wc[i * En];
#pragma unroll
        for (int e = 0; e < En; e++) p[e] += v * w[e];
    }
#pragma unroll
    for (int o = 16; o; o >>= 1)
#pragma unroll
        for (int e = 0; e < En; e++) p[e] += __shfl_xor_sync(0xffffffffu, p[e], o);
    if (lane == 0) {
#pragma unroll
        for (int e = 0; e < En; e++) p[e] += g_bc[e];
        int i1 = 0;
        for (int e = 1; e < En; e++) if (p[e] > p[i1]) i1 = e;
        int i2 = -1;
        for (int e = 0; e < En; e++)
            if (e != i1 && (i2 < 0 || p[e] > p[i2])) i2 = e;
        float w1 = 1.f / (1.f + expf(p[i2] - p[i1]));
        g_gi[warp * 2] = i1; g_gi[warp * 2 + 1] = i2;
        g_gw[warp * 2] = w1; g_gw[warp * 2 + 1] = 1.f - w1;
        atomicAdd(&g_cnt[i1], 1);
        atomicAdd(&g_cnt[i2], 1);
    }
}

__global__ void k_off() {
    int a = 0;
    for (int e = 0; e < En; e++) { g_off[e] = a; a += g_cnt[e]; g_fill[e] = 0; }
}

__global__ void k_scatter() {
    int t = blockIdx.x * blockDim.x + threadIdx.x;
    if (t >= Tn) return;
#pragma unroll
    for (int k = 0; k < 2; k++) {
        int e = g_gi[t * 2 + k];
        int slot = g_off[e] + atomicAdd(&g_fill[e], 1);
        g_tok[slot] = t;
        g_tw[slot]  = g_gw[t * 2 + k];
    }
}

// ========== tf32 mma.sync GEMM: 128x128 tile, 8 warps (4Mx2N) ==============
// MODE 0: g_lin = x @ W^T + b               (KD=Dn, NT=Dn, B=W is [n][k])
// MODE 1: g_h = relu(lin[g_tok] @ w1[e]+b1) (KD=Dn, NT=Fn, B is [k][n])
// MODE 2: g_accb += gw * (g_h @ w2[e]+b2)   (KD=Fn, NT=Dn, B is [k][n])
template<int KD, int NT, int MODE>
__global__ void __launch_bounds__(256) mma_ffn(const float* __restrict__ Asrc,
                                               const float* __restrict__ Bw,
                                               const float* __restrict__ bias)
{
    __shared__ float As[16][136];   // [k][m]
    __shared__ float Bs[16][136];   // [k][n]
    int e = (MODE == 0) ? 0 : blockIdx.z;
    int cnt = (MODE == 0) ? Tn : g_cnt[e];
    int row0 = blockIdx.x * 128;
    if (MODE != 0 && row0 >= cnt) return;
    int off = (MODE == 0) ? 0 : g_off[e];
    int col0 = blockIdx.y * 128;
    int tid = threadIdx.x;
    int warp = tid >> 5, lane = tid & 31;
    int warpM = warp >> 1, warpN = warp & 1;
    int grp = lane >> 2, tig = lane & 3;
    int mBase = warpM * 32, nBase = warpN * 64;

    // A staging pointers (round-5 layout: 4 threads/row, 16B each)
    int rA = tid >> 2, k4 = (tid & 3) * 4;
    const float *a0p, *a1p;
    if (MODE == 0) {
        a0p = Asrc + (size_t)(row0 + rA) * KD;
        a1p = Asrc + (size_t)(row0 + rA + 64) * KD;
    } else if (MODE == 1) {
        bool v0 = (row0 + rA) < cnt, v1 = (row0 + rA + 64) < cnt;
        a0p = &g_lin[(size_t)(v0 ? g_tok[off + row0 + rA] : 0) * KD];
        a1p = &g_lin[(size_t)(v1 ? g_tok[off + row0 + rA + 64] : 0) * KD];
    } else {
        int s0 = off + row0 + rA;      if (s0 >= 2 * Tn) s0 = 0;
        int s1 = off + row0 + rA + 64; if (s1 >= 2 * Tn) s1 = 0;
        a0p = &g_h[(size_t)s0 * KD];
        a1p = &g_h[(size_t)s1 * KD];
    }
    const float* wp = Bw + (size_t)e * KD * NT;
    int nn = tid & 127, kh = (tid >> 7) * 8;   // MODE 0 transposed staging

    float cc[2][8][4] = {};
    for (int k0 = 0; k0 < KD; k0 += 16) {
        float4 va = *(const float4*)&a0p[k0 + k4];
        As[k4 + 0][rA] = tf32r(va.x); As[k4 + 1][rA] = tf32r(va.y);
        As[k4 + 2][rA] = tf32r(va.z); As[k4 + 3][rA] = tf32r(va.w);
        float4 vb = *(const float4*)&a1p[k0 + k4];
        As[k4 + 0][rA + 64] = tf32r(vb.x); As[k4 + 1][rA + 64] = tf32r(vb.y);
        As[k4 + 2][rA + 64] = tf32r(vb.z); As[k4 + 3][rA + 64] = tf32r(vb.w);
        if (MODE == 0) {
            // B = W[n][k] (k contiguous) -> Bs[k][n]
            const float* s = &wp[(size_t)(col0 + nn) * KD + k0 + kh];
            float4 v0 = *(const float4*)s, v1 = *(const float4*)(s + 4);
            Bs[kh + 0][nn] = tf32r(v0.x); Bs[kh + 1][nn] = tf32r(v0.y);
            Bs[kh + 2][nn] = tf32r(v0.z); Bs[kh + 3][nn] = tf32r(v0.w);
            Bs[kh + 4][nn] = tf32r(v1.x); Bs[kh + 5][nn] = tf32r(v1.y);
            Bs[kh + 6][nn] = tf32r(v1.z); Bs[kh + 7][nn] = tf32r(v1.w);
        } else {
#pragma unroll
            for (int l = 0; l < 2; l++) {
                int idx = tid + l * 256;
                int r = idx >> 5, c4 = (idx & 31) * 4;
                float4 v = *(const float4*)&wp[(size_t)(k0 + r) * NT + col0 + c4];
                Bs[r][c4 + 0] = tf32r(v.x); Bs[r][c4 + 1] = tf32r(v.y);
                Bs[r][c4 + 2] = tf32r(v.z); Bs[r][c4 + 3] = tf32r(v.w);
            }
        }
        __syncthreads();
#pragma unroll
        for (int ks = 0; ks < 16; ks += 8) {
            uint32_t af[2][4];
#pragma unroll
            for (int mt = 0; mt < 2; mt++) {
                int m = mBase + mt * 16 + grp;
                af[mt][0] = __float_as_uint(As[ks + tig][m]);
                af[mt][1] = __float_as_uint(As[ks + tig][m + 8]);
                af[mt][2] = __float_as_uint(As[ks + tig + 4][m]);
                af[mt][3] = __float_as_uint(As[ks + tig + 4][m + 8]);
            }
#pragma unroll
            for (int nt = 0; nt < 8; nt++) {
                int n = nBase + nt * 8 + grp;
                uint32_t b0 = __float_as_uint(Bs[ks + tig][n]);
                uint32_t b1 = __float_as_uint(Bs[ks + tig + 4][n]);
                mma8(cc[0][nt], af[0], b0, b1);
                mma8(cc[1][nt], af[1], b0, b1);
            }
        }
        __syncthreads();
    }

    // epilogue: c0,c1 -> row grp; c2,c3 -> row grp+8; cols 2*tig, 2*tig+1
#pragma unroll
    for (int mt = 0; mt < 2; mt++)
#pragma unroll
    for (int half = 0; half < 2; half++) {
        int r = row0 + mBase + mt * 16 + grp + half * 8;
        if (r >= cnt) continue;
        int slot = off + r;
        if (MODE == 0) {
            float* o = g_lin + (size_t)r * Dn + col0;
#pragma unroll
            for (int nt = 0; nt < 8; nt++) {
                int c = nBase + nt * 8 + 2 * tig;
                float2 v;
                v.x = cc[mt][nt][half * 2 + 0] + bias[col0 + c];
                v.y = cc[mt][nt][half * 2 + 1] + bias[col0 + c + 1];
                *(float2*)(o + c) = v;
            }
        } else if (MODE == 1) {
            float* o = g_h + (size_t)slot * Fn + col0;
#pragma unroll
            for (int nt = 0; nt < 8; nt++) {
                int c = nBase + nt * 8 + 2 * tig;
                float2 v;
                v.x = fmaxf(cc[mt][nt][half * 2 + 0] + bias[e * Fn + col0 + c], 0.f);
                v.y = fmaxf(cc[mt][nt][half * 2 + 1] + bias[e * Fn + col0 + c + 1], 0.f);
                *(float2*)(o + c) = v;
            }
        } else {
            int tok = g_tok[slot];
            float gw = g_tw[slot];
            float* o = g_accb + (size_t)tok * Dn + col0;
#pragma unroll
            for (int nt = 0; nt < 8; nt++) {
                int c = nBase + nt * 8 + 2 * tig;
                atomicAdd(&o[c],     gw * (cc[mt][nt][half * 2 + 0] + bias[e * Dn + col0 + c]));
                atomicAdd(&o[c + 1], gw * (cc[mt][nt][half * 2 + 1] + bias[e * Dn + col0 + c + 1]));
            }
        }
    }
}

// ---------------- mean pool (x + moe) + loss ----------------
__global__ void k_sent(const float* __restrict__ x, float* out) {
    int i = blockIdx.x * blockDim.x + threadIdx.x;
    if (i == 0) out[0] = 0.f;
    if (i >= Bb * Dn) return;
    int b = i >> 10, d = i & 1023;
    const float* p = &g_accb[(size_t)(b * Sn) * Dn + d];
    const float* q = &x[(size_t)(b * Sn) * Dn + d];
    float s = 0.f;
    for (int si = 0; si < Sn; si++) s += p[si * Dn] + q[si * Dn];
    g_sent[i] = s * (1.f / Sn);
}

__global__ void k_loss(const int* __restrict__ y, float* out) {
    int b = blockIdx.x, tid = threadIdx.x;
    __shared__ float red[256];
    const float* s = &g_sent[b * Dn];
    float m = -1e30f;
    for (int i = tid; i < Dn; i += 256) m = fmaxf(m, s[i]);
    red[tid] = m; __syncthreads();
    for (int o = 128; o; o >>= 1) {
        if (tid < o) red[tid] = fmaxf(red[tid], red[tid + o]);
        __syncthreads();
    }
    float mx = red[0]; __syncthreads();
    float sum = 0.f;
    for (int i = tid; i < Dn; i += 256) sum += expf(s[i] - mx);
    red[tid] = sum; __syncthreads();
    for (int o = 128; o; o >>= 1) {
        if (tid < o) red[tid] += red[tid + o];
        __syncthreads();
    }
    if (tid == 0)
        atomicAdd(out, -(s[y[b]] - (mx + logf(red[0]))) * (1.f / Bb));
}

// ---------------- launch ----------------
extern "C" void kernel_launch(void* const* d_in, const int* in_sizes, int n_in,
                              void* d_out, int out_size) {
    const float* x  = (const float*)d_in[0];
    const int*   y  = (const int*)d_in[1];
    const float* W  = (const float*)d_in[2];
    const float* bb = (const float*)d_in[3];
    const float* Wg = (const float*)d_in[4];
    const float* w1 = (const float*)d_in[5];
    const float* b1 = (const float*)d_in[6];
    const float* w2 = (const float*)d_in[7];
    const float* b2 = (const float*)d_in[8];
    float* out = (float*)d_out;

    k_wc<<<Dn / 256, 256>>>(W, Wg, bb);
    k_init<<<256, 256>>>();
    k_gate2<<<(Tn * 32) / 256, 256>>>(x);
    mma_ffn<Dn, Dn, 0><<<dim3(Tn / 128, Dn / 128, 1), 256>>>(x, W, bb);
    k_off<<<1, 1>>>();
    k_scatter<<<Tn / 256, 256>>>();
    mma_ffn<Dn, Fn, 1><<<dim3(Tn / 128, Fn / 128, En), 256>>>(nullptr, w1, b1);
    mma_ffn<Fn, Dn, 2><<<dim3(Tn / 128, Dn / 128, En), 256>>>(nullptr, w2, b2);
    k_sent<<<(Bb * Dn + 255) / 256, 256>>>(x, out);
    k_loss<<<Bb, 256>>>(y, out);
}

// round 8
// speedup vs baseline: 5.7305x; 1.1273x over previous
#include <cuda_runtime.h>
#include <cstdint>

#define Tn 4096   // B*S tokens
#define Dn 1024
#define En 8
#define Fn 4096
#define Bb 8
#define Sn 512

// ---------------- scratch (device globals; no allocations) ----------------
__device__ float g_lin[Tn * Dn];
__device__ float g_accb[Tn * Dn];          // x + moe accumulation
__device__ float g_h[2 * Tn * Fn];
__device__ float g_wc[Dn * En];            // folded gate weight: x@Wc = gate logits
__device__ float g_bc[En];
__device__ int   g_tok[2 * Tn];
__device__ float g_tw[2 * Tn];
__device__ int   g_cnt[En], g_off[En], g_fill[En];
__device__ int   g_gi[Tn * 2];
__device__ float g_gw[Tn * 2];
__device__ float g_sent[Bb * Dn];

// ---------------- helpers ----------------
__device__ __forceinline__ uint32_t s2u(const void* p) {
    uint32_t a;
    asm("{ .reg .u64 t; cvta.to.shared.u64 t, %1; cvt.u32.u64 %0, t; }" : "=r"(a) : "l"(p));
    return a;
}
__device__ __forceinline__ float tf32r(float v) {
    uint32_t r;
    asm("cvt.rna.tf32.f32 %0, %1;" : "=r"(r) : "f"(v));
    return __uint_as_float(r);
}
__device__ __forceinline__ void mma8(float* c, const uint32_t* a,
                                     uint32_t b0, uint32_t b1) {
    asm volatile(
        "mma.sync.aligned.m16n8k8.row.col.f32.tf32.tf32.f32 "
        "{%0,%1,%2,%3},{%4,%5,%6,%7},{%8,%9},{%0,%1,%2,%3};"
        : "+f"(c[0]), "+f"(c[1]), "+f"(c[2]), "+f"(c[3])
        : "r"(a[0]), "r"(a[1]), "r"(a[2]), "r"(a[3]), "r"(b0), "r"(b1));
}
#define CPA(dst, src) \
    asm volatile("cp.async.cg.shared.global [%0], [%1], 16;" :: "r"(dst), "l"(src) : "memory")
#define CPCOMMIT() asm volatile("cp.async.commit_group;" ::: "memory")
#define CPWAIT0()  asm volatile("cp.async.wait_group 0;" ::: "memory")
#define CPWAIT1()  asm volatile("cp.async.wait_group 1;" ::: "memory")

// ---------------- Wc = W^T @ Wg (exact fp32), bc = b @ Wg ----------------
__global__ void __launch_bounds__(256) k_wc(const float* __restrict__ W,
                                            const float* __restrict__ Wg,
                                            const float* __restrict__ b) {
    __shared__ float swg[Dn * En];
    for (int i = threadIdx.x; i < Dn * En; i += 256) swg[i] = Wg[i];
    __syncthreads();
    int d = blockIdx.x * 256 + threadIdx.x;
    float acc[En] = {};
    for (int ep = 0; ep < Dn; ep++) {
        float wv = W[(size_t)ep * Dn + d];
        const float* wg = &swg[ep * En];
#pragma unroll
        for (int e = 0; e < En; e++) acc[e] += wv * wg[e];
    }
#pragma unroll
    for (int e = 0; e < En; e++) g_wc[d * En + e] = acc[e];
    if (blockIdx.x == 0 && threadIdx.x < En) {
        float s = 0.f;
        for (int ep = 0; ep < Dn; ep++) s += b[ep] * swg[ep * En + threadIdx.x];
        g_bc[threadIdx.x] = s;
    }
}

// ---------------- init: acc = x, zero counters ----------------
__global__ void k_init(const float* __restrict__ x) {
    if (blockIdx.x == 0 && threadIdx.x < En) g_cnt[threadIdx.x] = 0;
    int st = gridDim.x * blockDim.x;
    for (int i = blockIdx.x * blockDim.x + threadIdx.x; i < Tn * Dn; i += st)
        g_accb[i] = x[i];
}

// ---------------- gate from x via folded Wc (exact fp32 top-2) -------------
__global__ void k_gate2(const float* __restrict__ x) {
    int warp = (blockIdx.x * blockDim.x + threadIdx.x) >> 5;
    int lane = threadIdx.x & 31;
    if (warp >= Tn) return;
    const float* xr = &x[(size_t)warp * Dn];
    float p[En] = {};
    for (int i = lane; i < Dn; i += 32) {
        float v = xr[i];
        const float* w = &g_wc[i * En];
#pragma unroll
        for (int e = 0; e < En; e++) p[e] += v * w[e];
    }
#pragma unroll
    for (int o = 16; o; o >>= 1)
#pragma unroll
        for (int e = 0; e < En; e++) p[e] += __shfl_xor_sync(0xffffffffu, p[e], o);
    if (lane == 0) {
#pragma unroll
        for (int e = 0; e < En; e++) p[e] += g_bc[e];
        int i1 = 0;
        for (int e = 1; e < En; e++) if (p[e] > p[i1]) i1 = e;
        int i2 = -1;
        for (int e = 0; e < En; e++)
            if (e != i1 && (i2 < 0 || p[e] > p[i2])) i2 = e;
        float w1 = 1.f / (1.f + expf(p[i2] - p[i1]));
        g_gi[warp * 2] = i1; g_gi[warp * 2 + 1] = i2;
        g_gw[warp * 2] = w1; g_gw[warp * 2 + 1] = 1.f - w1;
        atomicAdd(&g_cnt[i1], 1);
        atomicAdd(&g_cnt[i2], 1);
    }
}

__global__ void k_off() {
    int a = 0;
    for (int e = 0; e < En; e++) { g_off[e] = a; a += g_cnt[e]; g_fill[e] = 0; }
}

__global__ void k_scatter() {
    int t = blockIdx.x * blockDim.x + threadIdx.x;
    if (t >= Tn) return;
#pragma unroll
    for (int k = 0; k < 2; k++) {
        int e = g_gi[t * 2 + k];
        int slot = g_off[e] + atomicAdd(&g_fill[e], 1);
        g_tok[slot] = t;
        g_tw[slot]  = g_gw[t * 2 + k];
    }
}

// ---------------- lin = x @ W^T + b (tf32 mma, proven R7 path) -------------
__global__ void __launch_bounds__(256) k_lin_mma(const float* __restrict__ x,
                                                 const float* __restrict__ W,
                                                 const float* __restrict__ bias)
{
    __shared__ float As[16][136];
    __shared__ float Bs[16][136];
    int row0 = blockIdx.x * 128, col0 = blockIdx.y * 128;
    int tid = threadIdx.x;
    int warp = tid >> 5, lane = tid & 31;
    int warpM = warp >> 1, warpN = warp & 1;
    int grp = lane >> 2, tig = lane & 3;
    int mBase = warpM * 32, nBase = warpN * 64;
    int rA = tid >> 2, k4 = (tid & 3) * 4;
    const float* a0p = x + (size_t)(row0 + rA) * Dn;
    const float* a1p = x + (size_t)(row0 + rA + 64) * Dn;
    int nn = tid & 127, kh = (tid >> 7) * 8;

    float cc[2][8][4] = {};
    for (int k0 = 0; k0 < Dn; k0 += 16) {
        float4 va = *(const float4*)&a0p[k0 + k4];
        As[k4 + 0][rA] = tf32r(va.x); As[k4 + 1][rA] = tf32r(va.y);
        As[k4 + 2][rA] = tf32r(va.z); As[k4 + 3][rA] = tf32r(va.w);
        float4 vb = *(const float4*)&a1p[k0 + k4];
        As[k4 + 0][rA + 64] = tf32r(vb.x); As[k4 + 1][rA + 64] = tf32r(vb.y);
        As[k4 + 2][rA + 64] = tf32r(vb.z); As[k4 + 3][rA + 64] = tf32r(vb.w);
        const float* s = &W[(size_t)(col0 + nn) * Dn + k0 + kh];
        float4 v0 = *(const float4*)s, v1 = *(const float4*)(s + 4);
        Bs[kh + 0][nn] = tf32r(v0.x); Bs[kh + 1][nn] = tf32r(v0.y);
        Bs[kh + 2][nn] = tf32r(v0.z); Bs[kh + 3][nn] = tf32r(v0.w);
        Bs[kh + 4][nn] = tf32r(v1.x); Bs[kh + 5][nn] = tf32r(v1.y);
        Bs[kh + 6][nn] = tf32r(v1.z); Bs[kh + 7][nn] = tf32r(v1.w);
        __syncthreads();
#pragma unroll
        for (int ks = 0; ks < 16; ks += 8) {
            uint32_t af[2][4];
#pragma unroll
            for (int mt = 0; mt < 2; mt++) {
                int m = mBase + mt * 16 + grp;
                af[mt][0] = __float_as_uint(As[ks + tig][m]);
                af[mt][1] = __float_as_uint(As[ks + tig][m + 8]);
                af[mt][2] = __float_as_uint(As[ks + tig + 4][m]);
                af[mt][3] = __float_as_uint(As[ks + tig + 4][m + 8]);
            }
#pragma unroll
            for (int nt = 0; nt < 8; nt++) {
                int n = nBase + nt * 8 + grp;
                uint32_t b0 = __float_as_uint(Bs[ks + tig][n]);
                uint32_t b1 = __float_as_uint(Bs[ks + tig + 4][n]);
                mma8(cc[0][nt], af[0], b0, b1);
                mma8(cc[1][nt], af[1], b0, b1);
            }
        }
        __syncthreads();
    }
#pragma unroll
    for (int mt = 0; mt < 2; mt++)
#pragma unroll
    for (int half = 0; half < 2; half++) {
        int r = row0 + mBase + mt * 16 + grp + half * 8;
        float* o = g_lin + (size_t)r * Dn + col0;
#pragma unroll
        for (int nt = 0; nt < 8; nt++) {
            int c = nBase + nt * 8 + 2 * tig;
            float2 v;
            v.x = cc[mt][nt][half * 2 + 0] + bias[col0 + c];
            v.y = cc[mt][nt][half * 2 + 1] + bias[col0 + c + 1];
            *(float2*)(o + c) = v;
        }
    }
}

// ==== pipelined tf32 grouped GEMM: cp.async 2-stage, Kc=32 =================
// MODE 1: g_h = relu(lin[g_tok] @ w1[e] + b1)   (KD=Dn, NT=Fn)
// MODE 2: g_accb += gw * (g_h @ w2[e] + b2)     (KD=Fn, NT=Dn)
template<int KD, int NT, int MODE>
__global__ void __launch_bounds__(256) pipe_ffn(const float* __restrict__ Bw,
                                                const float* __restrict__ bias)
{
    extern __shared__ float sm[];
    constexpr int ASTR = 36, BSTR = 136;          // pads: A frag & B frag conflict-free
    constexpr uint32_t ASTG = 128 * ASTR * 4, BSTG = 32 * BSTR * 4;
    float* Asm = sm;                               // [2][128][36]  ([m][k])
    float* Bsm = sm + 2 * 128 * ASTR;              // [2][32][136]  ([k][n])

    int e = blockIdx.z, cnt = g_cnt[e], row0 = blockIdx.x * 128;
    if (row0 >= cnt) return;
    int off = g_off[e], col0 = blockIdx.y * 128;
    int tid = threadIdx.x, warp = tid >> 5, lane = tid & 31;
    int warpM = warp >> 1, warpN = warp & 1;
    int grp = lane >> 2, tig = lane & 3;
    int mBase = warpM * 32, nBase = warpN * 64;

    uint32_t Au = s2u(Asm), Bu = s2u(Bsm);

    // A staging: row ar = tid>>1, floats [ac, ac+16)
    int ar = tid >> 1, ac = (tid & 1) * 16;
    const float* asrc;
    if (MODE == 1) {
        int r = row0 + ar;
        int tok = (r < cnt) ? g_tok[off + r] : g_tok[off];
        asrc = g_lin + (size_t)tok * KD;
    } else {
        int s = off + row0 + ar; if (s >= 2 * Tn) s = 0;
        asrc = g_h + (size_t)s * KD;
    }
    // B staging: row br = tid>>3, float chunks bc4 + 32*j
    int br = tid >> 3, bc4 = (tid & 7) * 4;
    const float* bsrc = Bw + (size_t)e * KD * NT + (size_t)br * NT + col0 + bc4;

    uint32_t aDst0 = Au + ((uint32_t)ar * ASTR + ac) * 4;
    uint32_t bDst0 = Bu + ((uint32_t)br * BSTR + bc4) * 4;

    auto stage = [&](int it) {
        int buf = it & 1;
        int k0 = it * 32;
        uint32_t ad = aDst0 + buf * ASTG;
        const float* as = asrc + k0 + ac;
#pragma unroll
        for (int j = 0; j < 4; j++) CPA(ad + j * 16, as + j * 4);
        uint32_t bd = bDst0 + buf * BSTG;
        const float* bs = bsrc + (size_t)k0 * NT;
#pragma unroll
        for (int j = 0; j < 4; j++) CPA(bd + j * 128, bs + j * 32);
        CPCOMMIT();
    };

    stage(0);
    stage(1);

    float cc[2][8][4] = {};
    constexpr int NK = KD / 32;
    for (int it = 0; it < NK; ++it) {
        if (it == NK - 1) { CPWAIT0(); } else { CPWAIT1(); }
        __syncthreads();
        int buf = it & 1;
        const float* Af = Asm + buf * 128 * ASTR;
        const float* Bf = Bsm + buf * 32 * BSTR;
#pragma unroll
        for (int ks = 0; ks < 32; ks += 8) {
            uint32_t af[2][4];
#pragma unroll
            for (int mt = 0; mt < 2; mt++) {
                int m = mBase + mt * 16 + grp;
                af[mt][0] = __float_as_uint(Af[m * ASTR + ks + tig]);
                af[mt][1] = __float_as_uint(Af[(m + 8) * ASTR + ks + tig]);
                af[mt][2] = __float_as_uint(Af[m * ASTR + ks + tig + 4]);
                af[mt][3] = __float_as_uint(Af[(m + 8) * ASTR + ks + tig + 4]);
            }
#pragma unroll
            for (int nt = 0; nt < 8; nt++) {
                int n = nBase + nt * 8 + grp;
                uint32_t b0 = __float_as_uint(Bf[(ks + tig) * BSTR + n]);
                uint32_t b1 = __float_as_uint(Bf[(ks + tig + 4) * BSTR + n]);
                mma8(cc[0][nt], af[0], b0, b1);
                mma8(cc[1][nt], af[1], b0, b1);
            }
        }
        __syncthreads();
        if (it + 2 < NK) stage(it + 2);
    }

    // epilogue
#pragma unroll
    for (int mt = 0; mt < 2; mt++)
#pragma unroll
    for (int half = 0; half < 2; half++) {
        int r = row0 + mBase + mt * 16 + grp + half * 8;
        if (r >= cnt) continue;
        int slot = off + r;
        if (MODE == 1) {
            float* o = g_h + (size_t)slot * Fn + col0;
#pragma unroll
            for (int nt = 0; nt < 8; nt++) {
                int c = nBase + nt * 8 + 2 * tig;
                float2 v;
                v.x = fmaxf(cc[mt][nt][half * 2 + 0] + bias[e * Fn + col0 + c], 0.f);
                v.y = fmaxf(cc[mt][nt][half * 2 + 1] + bias[e * Fn + col0 + c + 1], 0.f);
                *(float2*)(o + c) = v;
            }
        } else {
            int tok = g_tok[slot];
            float gw = g_tw[slot];
            float* o = g_accb + (size_t)tok * Dn + col0;
#pragma unroll
            for (int nt = 0; nt < 8; nt++) {
                int c = nBase + nt * 8 + 2 * tig;
                atomicAdd(&o[c],     gw * (cc[mt][nt][half * 2 + 0] + bias[e * Dn + col0 + c]));
                atomicAdd(&o[c + 1], gw * (cc[mt][nt][half * 2 + 1] + bias[e * Dn + col0 + c + 1]));
            }
        }
    }
}

// ---------------- mean pool + loss ----------------
__global__ void k_sent(float* out) {
    int i = blockIdx.x * blockDim.x + threadIdx.x;
    if (i == 0) out[0] = 0.f;
    if (i >= Bb * Dn) return;
    int b = i >> 10, d = i & 1023;
    const float* p = &g_accb[(size_t)(b * Sn) * Dn + d];
    float s = 0.f;
    for (int si = 0; si < Sn; si++) s += p[si * Dn];
    g_sent[i] = s * (1.f / Sn);
}

__global__ void k_loss(const int* __restrict__ y, float* out) {
    int b = blockIdx.x, tid = threadIdx.x;
    __shared__ float red[256];
    const float* s = &g_sent[b * Dn];
    float m = -1e30f;
    for (int i = tid; i < Dn; i += 256) m = fmaxf(m, s[i]);
    red[tid] = m; __syncthreads();
    for (int o = 128; o; o >>= 1) {
        if (tid < o) red[tid] = fmaxf(red[tid], red[tid + o]);
        __syncthreads();
    }
    float mx = red[0]; __syncthreads();
    float sum = 0.f;
    for (int i = tid; i < Dn; i += 256) sum += expf(s[i] - mx);
    red[tid] = sum; __syncthreads();
    for (int o = 128; o; o >>= 1) {
        if (tid < o) red[tid] += red[tid + o];
        __syncthreads();
    }
    if (tid == 0)
        atomicAdd(out, -(s[y[b]] - (mx + logf(red[0]))) * (1.f / Bb));
}

// ---------------- launch ----------------
extern "C" void kernel_launch(void* const* d_in, const int* in_sizes, int n_in,
                              void* d_out, int out_size) {
    const float* x  = (const float*)d_in[0];
    const int*   y  = (const int*)d_in[1];
    const float* W  = (const float*)d_in[2];
    const float* bb = (const float*)d_in[3];
    const float* Wg = (const float*)d_in[4];
    const float* w1 = (const float*)d_in[5];
    const float* b1 = (const float*)d_in[6];
    const float* w2 = (const float*)d_in[7];
    const float* b2 = (const float*)d_in[8];
    float* out = (float*)d_out;

    constexpr int SMEMB = (2 * 128 * 36 + 2 * 32 * 136) * 4;  // 71680 B
    static int done = 0;
    if (!done) {
        cudaFuncSetAttribute((const void*)pipe_ffn<Dn, Fn, 1>,
                             cudaFuncAttributeMaxDynamicSharedMemorySize, SMEMB);
        cudaFuncSetAttribute((const void*)pipe_ffn<Fn, Dn, 2>,
                             cudaFuncAttributeMaxDynamicSharedMemorySize, SMEMB);
        done = 1;
    }

    k_wc<<<Dn / 256, 256>>>(W, Wg, bb);
    k_init<<<256, 256>>>(x);
    k_gate2<<<(Tn * 32) / 256, 256>>>(x);
    k_lin_mma<<<dim3(Tn / 128, Dn / 128), 256>>>(x, W, bb);
    k_off<<<1, 1>>>();
    k_scatter<<<Tn / 256, 256>>>();
    pipe_ffn<Dn, Fn, 1><<<dim3(Tn / 128, Fn / 128, En), 256, SMEMB>>>(w1, b1);
    pipe_ffn<Fn, Dn, 2><<<dim3(Tn / 128, Dn / 128, En), 256, SMEMB>>>(w2, b2);
    k_sent<<<(Bb * Dn + 255) / 256, 256>>>(out);
    k_loss<<<Bb, 256>>>(y, out);
}